// round 6
// baseline (speedup 1.0000x reference)
#include <cuda_runtime.h>
#include <math.h>

#define NB 8
#define NC 12
#define NNtok 785
#define NS 784
#define NH 28
#define ND 768
#define KHID 512
#define PNUM 84
#define SCL 0.7f
#define NT 800          // 25 warps; thread tid<784 owns element tid
#define NW 25

// ---------------- device scratch ----------------
__device__ float         g_ns[NB * NC * NS];
__device__ unsigned char g_sel[NB * NC * NS];
__device__ float         g_u1p[NB * KHID];
__device__ float         g_u1m[NB * KHID];
__device__ float         g_scal[NB * 4];
__device__ int           g_patch[NB * NS];

// ================= Kernel A: per (b,c) top-84 via 4-pass radix select ==========
__global__ __launch_bounds__(NT) void kTopSel(const float* __restrict__ x)
{
    __shared__ unsigned su[NS];
    __shared__ int      hist[256];
    __shared__ int      wpre[8];
    __shared__ unsigned s_pref;
    __shared__ int      s_rem;
    const int bc = blockIdx.x, tid = threadIdx.x;
    const int lane = tid & 31;
    const bool act = (tid < NS);

    float    myv = 0.f;
    unsigned myu = 0u;
    if (act) {
        myv = x[(long long)bc * NNtok * NNtok + 1 + tid];   // x[b,c,0,1+tid]
        unsigned ub = __float_as_uint(myv);
        myu = (ub & 0x80000000u) ? ~ub : (ub | 0x80000000u);
        su[tid] = myu;
    }
    if (tid == 0) { s_pref = 0u; s_rem = PNUM; }
    __syncthreads();

    #pragma unroll
    for (int pass = 0; pass < 4; pass++) {
        const int shift = 24 - 8 * pass;
        const unsigned mask_hi = (pass == 0) ? 0u : (0xFFFFFFFFu << (shift + 8));
        const unsigned pref = s_pref;
        const int rem = s_rem;
        if (tid < 256) hist[tid] = 0;
        __syncthreads();
        // warp-aggregated histogram: one atomic per distinct bin per warp
        {
            unsigned pbin = 0xFFFFu;   // sentinel for non-participants
            if (act && (myu & mask_hi) == pref) pbin = (myu >> shift) & 0xFFu;
            unsigned mm = __match_any_sync(0xFFFFFFFFu, pbin);
            if (pbin < 256u && lane == (__ffs(mm) - 1))
                atomicAdd(&hist[pbin], __popc(mm));
        }
        __syncthreads();
        // suffix count via warp scan: gt(v) = total - inclusive_prefix(v)
        int h = 0, s = 0;
        if (tid < 256) {
            h = hist[tid];
            s = h;
            #pragma unroll
            for (int o = 1; o < 32; o <<= 1) {
                int n = __shfl_up_sync(0xFFFFFFFFu, s, o);
                if (lane >= o) s += n;
            }
            if (lane == 31) wpre[tid >> 5] = s;
        }
        __syncthreads();
        if (tid < 256) {
            int off = 0, total = 0;
            #pragma unroll
            for (int r = 0; r < 8; r++) {
                int w = wpre[r]; total += w; if (r < (tid >> 5)) off += w;
            }
            const int gt = total - (s + off);   // # keys strictly greater than bin
            if (gt < rem && gt + h >= rem) {
                s_pref = pref | ((unsigned)tid << shift);
                s_rem  = rem - gt;
            }
        }
        __syncthreads();
    }
    const unsigned T = s_pref;      // exact 84th-largest key
    const int need  = s_rem;        // ties taken ascending-index (= lax.top_k)

    if (act) {
        bool sel;
        if (myu > T) sel = true;
        else if (myu == T) {
            int e = 0;
            for (int j = 0; j < tid; j++) e += (su[j] == T) ? 1 : 0;  // rare
            sel = (e < need);
        } else sel = false;
        g_ns[bc * NS + tid]  = sel ? myv : myv * SCL;
        g_sel[bc * NS + tid] = sel ? (unsigned char)1 : (unsigned char)0;
    }
}

// ===== Kernel B: per-b stats + anchor + u1 + count-conv + stable ranks =========
__global__ __launch_bounds__(NT) void kPerB(const float* __restrict__ w1, int seln)
{
    __shared__ float msh[NS];
    __shared__ int   c0[NS];
    __shared__ int   whist[NW][256];
    __shared__ int   sfx[256];
    __shared__ float redf[NW], redf2[NW], redf3[NW], redf4[NW];
    __shared__ int   redi[NW], redw[8];
    __shared__ float s_mean, s_w0, s_w1;
    __shared__ int   s_anchor;
    const int b = blockIdx.x, tid = threadIdx.x;
    const int warp = tid >> 5, lane = tid & 31;
    const bool act = (tid < NS);

    // ---- m[s] = sum_c new_score; mean ----
    float m = 0.f;
    if (act) {
        #pragma unroll
        for (int c = 0; c < NC; c++) m += g_ns[(b * NC + c) * NS + tid];
        msh[tid] = m;
    }
    float psum = act ? m : 0.f;
    for (int o = 16; o; o >>= 1) psum += __shfl_xor_sync(0xFFFFFFFFu, psum, o);
    if (lane == 0) redf[warp] = psum;
    __syncthreads();
    if (tid == 0) {
        float t = 0.f;
        for (int w = 0; w < NW; w++) t += redf[w];
        s_mean = t / (float)NS;
    }
    __syncthreads();
    const float mean = s_mean;

    // ---- anchor = argmax(binary*m/C), first-index tie-break ----
    float bv = -1e30f; int bi = NS;
    if (act) {
        float v = (m > mean) ? m * (1.0f / NC) : 0.0f;
        bv = v; bi = tid;
    }
    for (int o = 16; o; o >>= 1) {
        float ov = __shfl_xor_sync(0xFFFFFFFFu, bv, o);
        int   oi = __shfl_xor_sync(0xFFFFFFFFu, bi, o);
        if (ov > bv || (ov == bv && oi < bi)) { bv = ov; bi = oi; }
    }
    if (lane == 0) { redf[warp] = bv; redi[warp] = bi; }
    __syncthreads();
    if (tid == 0) {
        float v = redf[0]; int i = redi[0];
        for (int w = 1; w < NW; w++)
            if (redf[w] > v || (redf[w] == v && redi[w] < i)) { v = redf[w]; i = redi[w]; }
        s_anchor = i;
    }
    __syncthreads();
    const int anchor = s_anchor;
    const float ai = (float)(anchor / NH), aj = (float)(anchor % NH);

    // ---- w0 = Σ pw·dist, w1 = Σ pw·ang, c± = Σ pw² by sign ----
    float w0 = 0.f, w1s = 0.f, cpv = 0.f, cmv = 0.f;
    if (act) {
        float p   = m * (1.0f / NC);
        float rc0 = ((float)(tid / NH) - ai) / (float)NH;
        float rc1 = ((float)(tid % NH) - aj) / (float)NH;
        w0  = p * sqrtf(rc0 * rc0 + rc1 * rc1);
        w1s = p * (atan2f(rc1, rc0) * 0.3183098861837907f + 1.0f) * 0.5f;
        if (p > 0.f) cpv = p * p; else if (p < 0.f) cmv = p * p;
    }
    for (int o = 16; o; o >>= 1) {
        w0  += __shfl_xor_sync(0xFFFFFFFFu, w0,  o);
        w1s += __shfl_xor_sync(0xFFFFFFFFu, w1s, o);
        cpv += __shfl_xor_sync(0xFFFFFFFFu, cpv, o);
        cmv += __shfl_xor_sync(0xFFFFFFFFu, cmv, o);
    }
    if (lane == 0) { redf[warp] = w0; redf2[warp] = w1s; redf3[warp] = cpv; redf4[warp] = cmv; }
    __syncthreads();
    if (tid == 0) {
        float a = 0, bb = 0, c = 0, d = 0;
        for (int w = 0; w < NW; w++) { a += redf[w]; bb += redf2[w]; c += redf3[w]; d += redf4[w]; }
        s_w0 = a; s_w1 = bb;
        g_scal[b * 4 + 0] = msh[anchor] * (1.0f / NC);
        g_scal[b * 4 + 1] = c;
        g_scal[b * 4 + 2] = d;
    }

    // ---- count c0 + zero whist ----
    if (act) {
        int t = 0;
        #pragma unroll
        for (int c = 0; c < NC; c++) t += (int)g_sel[(b * NC + c) * NS + tid];
        c0[tid] = t;
    }
    for (int i = tid; i < NW * 256; i += NT) ((int*)whist)[i] = 0;
    __syncthreads();

    // ---- u1 halves ----
    if (tid < KHID) {
        float u = s_w0 * w1[tid] + s_w1 * w1[KHID + tid];
        g_u1p[b * KHID + tid] = fmaxf(u, 0.f);
        g_u1m[b * KHID + tid] = fmaxf(-u, 0.f);
    }

    // ---- 3x3 conv + warp-aggregated per-warp value histogram ----
    int vcc = 0;
    unsigned mm;
    {
        if (act) {
            int i0 = tid / NH, j0 = tid % NH;
            #pragma unroll
            for (int di = -1; di <= 1; di++)
                #pragma unroll
                for (int dj = -1; dj <= 1; dj++) {
                    int ii = i0 + di, jj = j0 + dj;
                    if (ii >= 0 && ii < NH && jj >= 0 && jj < NH)
                        vcc += (2 - abs(di)) * (2 - abs(dj)) * c0[ii * NH + jj];
                }
        }
        int key = act ? vcc : 999;              // sentinel matches only sentinels
        mm = __match_any_sync(0xFFFFFFFFu, key);
        if (act && lane == (__ffs(mm) - 1))
            atomicAdd(&whist[warp][vcc], __popc(mm));   // one atomic per (warp,value)
    }
    __syncthreads();

    // ---- sfx[v] = # strictly greater (warp-scan suffix over 256 bins) ----
    int h = 0, s = 0;
    if (tid < 256) {
        #pragma unroll
        for (int r = 0; r < NW; r++) h += whist[r][tid];
        s = h;
        #pragma unroll
        for (int o = 1; o < 32; o <<= 1) {
            int n = __shfl_up_sync(0xFFFFFFFFu, s, o);
            if (lane >= o) s += n;
        }
        if (lane == 31) redw[tid >> 5] = s;
    }
    __syncthreads();
    if (tid < 256) {
        int off = 0, total = 0;
        #pragma unroll
        for (int r = 0; r < 8; r++) {
            int w = redw[r]; total += w; if (r < (tid >> 5)) off += w;
        }
        sfx[tid] = total - (s + off);
    }
    __syncthreads();

    // ---- stable descending rank: reuse match mask, popc for in-warp ties ----
    if (act) {
        int g = sfx[vcc];
        if (g < seln) {
            int e = __popc(mm & ((1u << lane) - 1u));
            for (int r = 0; r < warp; r++) e += whist[r][vcc];
            int rk = g + e;                 // ties by ascending index (stable)
            if (rk < seln) g_patch[b * NS + rk] = tid + 1;
        }
    }
}

// ===== Kernel C: fused struct-GEMV(+row0 write), hs copy, selected gather ======
#define SBLK 96
#define NCOPY4 (NB * NS * (ND / 4))           // 1,204,224 float4 (rows 1..784)
#define CBLK (NCOPY4 / 2048)                  // 588 blocks, 8 float4/thread
__global__ __launch_bounds__(256) void kFinal(const float* __restrict__ w2,
                                              const float4* __restrict__ hin,
                                              float4* __restrict__ out,
                                              int seln, int ngat4)
{
    const int bi = blockIdx.x, tid = threadIdx.x;

    if (bi < SBLK) {
        // ---- struct row @ anchor: leaky(pw_a*(c+·(u1p@W2) − c−·(u1m@W2))) ----
        __shared__ float up[KHID], um[KHID];
        __shared__ float sap[4][64], sam[4][64];
        const int b  = bi / 12;
        const int j0 = (bi % 12) * 64;
        for (int k = tid; k < KHID; k += 256) {
            up[k] = g_u1p[b * KHID + k];
            um[k] = g_u1m[b * KHID + k];
        }
        __syncthreads();
        const int jj = tid & 63, ks = tid >> 6;
        float ap = 0.f, am = 0.f;
        const float* wp = w2 + j0 + jj;
        #pragma unroll 4
        for (int k = ks * 128; k < ks * 128 + 128; k++) {
            float w = wp[(long long)k * ND];
            ap += up[k] * w;
            am += um[k] * w;
        }
        sap[ks][jj] = ap; sam[ks][jj] = am;
        __syncthreads();
        if (ks == 0) {
            float a = sap[0][jj] + sap[1][jj] + sap[2][jj] + sap[3][jj];
            float mmv = sam[0][jj] + sam[1][jj] + sam[2][jj] + sam[3][jj];
            float pa = g_scal[b * 4 + 0], cpv = g_scal[b * 4 + 1], cmv = g_scal[b * 4 + 2];
            float val = pa * (cpv * a - cmv * mmv);
            val = val > 0.f ? val : 0.2f * val;
            const int fi = (b * NNtok) * ND + j0 + jj;          // row 0 of batch b
            ((float*)out)[fi] = ((const float*)hin)[fi] + val;
        }
    } else if (bi < SBLK + CBLK) {
        // ---- hs rows 1..784 copy: 8 float4/thread, block-strided (MLP 8) ----
        const int base = (bi - SBLK) * 2048 + tid;
        float4 v[8];
        int oi[8];
        #pragma unroll
        for (int j = 0; j < 8; j++) {
            int k  = base + j * 256;
            int b  = k / (NS * (ND / 4));
            int r  = k - b * (NS * (ND / 4));
            int n  = r / (ND / 4);
            int d4 = r - n * (ND / 4);
            int idx = (b * NNtok + n + 1) * (ND / 4) + d4;
            v[j]  = hin[idx];
            oi[j] = idx;
        }
        #pragma unroll
        for (int j = 0; j < 8; j++) out[oi[j]] = v[j];
    } else {
        // ---- selected gather: 4 float4/thread ----
        const int base = (bi - SBLK - CBLK) * 1024 + tid;
        #pragma unroll
        for (int j = 0; j < 4; j++) {
            int k = base + j * 256;
            if (k < ngat4) {
                int row = k / (ND / 4), d4 = k - row * (ND / 4);
                int b = row / seln, q = row - b * seln;
                int p = g_patch[b * NS + q];     // in [1,784]: unmodified hs rows
                out[NB * NNtok * (ND / 4) + k] = hin[(b * NNtok + p) * (ND / 4) + d4];
            }
        }
    }
}

// ---------------- launch ----------------
extern "C" void kernel_launch(void* const* d_in, const int* in_sizes, int n_in,
                              void* d_out, int out_size)
{
    const float* hs = (const float*)d_in[0];
    const float* x  = (const float*)d_in[1];
    const float* w1 = (const float*)d_in[2];
    const float* w2 = (const float*)d_in[3];

    const int hs_elems = NB * NNtok * ND;
    int seln = (out_size - hs_elems) / (NB * ND);
    if (seln < 1) seln = 1;

    kTopSel<<<NB * NC, NT>>>(x);
    kPerB<<<NB, NT>>>(w1, seln);
    int ngat4 = NB * seln * (ND / 4);
    int gblk  = (ngat4 + 1023) / 1024;
    kFinal<<<SBLK + CBLK + gblk, 256>>>(w2, (const float4*)hs, (float4*)d_out,
                                        seln, ngat4);
}